// round 4
// baseline (speedup 1.0000x reference)
#include <cuda_runtime.h>
#include <math.h>
#include <stdint.h>

// ---------------------------------------------------------------------------
// Model_25975962206896: 4-qubit VQC, B=524288.
// Z = s† (W† M W) s with s = v⊗v⊗v⊗v rank-1 ⇒ Z collapses to a 15-term
// trigonometric polynomial in (f0, f1).
// SINGLE fused kernel: warp 0 of every block rebuilds the 30 coefficients
// (redundant but concurrent, ~1k cycles), then all threads stream eval.
// ---------------------------------------------------------------------------

__device__ __forceinline__ float2 cmulf(float2 a, float2 b) {
    return make_float2(a.x * b.x - a.y * b.y, a.x * b.y + a.y * b.x);
}
__device__ __forceinline__ float2 caddf(float2 a, float2 b) {
    return make_float2(a.x + b.x, a.y + b.y);
}

// ---------------------------------------------------------------------------
// Per-element evaluation: 15-term trig polynomial.
// ---------------------------------------------------------------------------
__device__ __forceinline__ float eval_one(float f0, float f1,
                                          const float* __restrict__ A,
                                          const float* __restrict__ B) {
    float s, c, s1, c1;
    __sincosf(0.5f * f1, &s, &c);
    __sincosf(f0, &s1, &c1);

    // Chebyshev: cos/sin of m*f0, m=2..4
    float c2 = fmaf(2.0f * c1, c1, -1.0f);
    float s2 = 2.0f * s1 * c1;
    float c3 = fmaf(c2, c1, -s2 * s1);
    float s3 = fmaf(s2, c1, c2 * s1);
    float c4 = fmaf(c3, c1, -s3 * s1);
    float s4 = fmaf(s3, c1, c3 * s1);

    // w[p] = c^(8-p) * s^p, p = 0..8
    float cp[9], sp[9];
    cp[0] = 1.0f; sp[0] = 1.0f;
#pragma unroll
    for (int i = 1; i < 9; i++) { cp[i] = cp[i - 1] * c; sp[i] = sp[i - 1] * s; }
    float w0 = cp[8];
    float w1 = cp[7] * sp[1];
    float w2 = cp[6] * sp[2];
    float w3 = cp[5] * sp[3];
    float w4 = cp[4] * sp[4];
    float w5 = cp[3] * sp[5];
    float w6 = cp[2] * sp[6];
    float w7 = cp[1] * sp[7];
    float w8 = sp[8];

    // m=0 terms (B=0, trig=A): k = 0,5,9,12,14 with p = 0,2,4,6,8
    float Z = A[0] * w0;
    Z = fmaf(A[5],  w2, Z);
    Z = fmaf(A[9],  w4, Z);
    Z = fmaf(A[12], w6, Z);
    Z = fmaf(A[14], w8, Z);
    // m=1: k = 1,6,10,13 with p = 1,3,5,7
    Z = fmaf(fmaf(A[1],  c1, B[1]  * s1), w1, Z);
    Z = fmaf(fmaf(A[6],  c1, B[6]  * s1), w3, Z);
    Z = fmaf(fmaf(A[10], c1, B[10] * s1), w5, Z);
    Z = fmaf(fmaf(A[13], c1, B[13] * s1), w7, Z);
    // m=2: k = 2,7,11 with p = 2,4,6
    Z = fmaf(fmaf(A[2],  c2, B[2]  * s2), w2, Z);
    Z = fmaf(fmaf(A[7],  c2, B[7]  * s2), w4, Z);
    Z = fmaf(fmaf(A[11], c2, B[11] * s2), w6, Z);
    // m=3: k = 3,8 with p = 3,5
    Z = fmaf(fmaf(A[3],  c3, B[3]  * s3), w3, Z);
    Z = fmaf(fmaf(A[8],  c3, B[8]  * s3), w5, Z);
    // m=4: k = 4, p = 4
    Z = fmaf(fmaf(A[4],  c4, B[4]  * s4), w4, Z);
    return Z;
}

// ---------------------------------------------------------------------------
// Fused kernel: warp 0 builds coefficients in shared, then everyone evals.
// ---------------------------------------------------------------------------
__global__ __launch_bounds__(256) void fused_kernel(
    const float4* __restrict__ in, const float* __restrict__ wU,
    const float* __restrict__ wR, const float* __restrict__ scp,
    const float* __restrict__ bip, float2* __restrict__ out) {

    __shared__ float2 gates[6][4][2][2];
    __shared__ float  isc[6], iss[6];
    __shared__ float2 sW[16][16];    // sW[row i][col t]
    __shared__ float2 sS[16][5];     // popcount-binned row sums
    __shared__ float  sA[15], sB[15];
    __shared__ float  sScale, sBias;

    const int tid = threadIdx.x;

    if (tid < 32) {
        const int t = tid;
        // ---- phase A: 2x2 gates + iSWAP angles + scalars ----
        if (t < 24) {
            int l = t / 4, qb = t % 4;
            float a = wR[l * 12 + qb * 3 + 0];
            float b = wR[l * 12 + qb * 3 + 1];
            float cg = wR[l * 12 + qb * 3 + 2];
            float sa, ca, sb, cb, sc3, cc3;
            sincosf(0.5f * a, &sa, &ca);
            sincosf(0.5f * b, &sb, &cb);
            sincosf(0.5f * cg, &sc3, &cc3);
            // g = RX(a) * RZ(b) * RX(c)
            float2 m1_00 = make_float2(ca, 0.f), m1_01 = make_float2(0.f, -sa);
            float2 m1_10 = make_float2(0.f, -sa), m1_11 = make_float2(ca, 0.f);
            float2 e0 = make_float2(cb, -sb), e1 = make_float2(cb, sb);
            float2 m3_00 = make_float2(cc3, 0.f), m3_01 = make_float2(0.f, -sc3);
            float2 m3_10 = make_float2(0.f, -sc3), m3_11 = make_float2(cc3, 0.f);
            float2 m23_00 = cmulf(e0, m3_00), m23_01 = cmulf(e0, m3_01);
            float2 m23_10 = cmulf(e1, m3_10), m23_11 = cmulf(e1, m3_11);
            gates[l][qb][0][0] = caddf(cmulf(m1_00, m23_00), cmulf(m1_01, m23_10));
            gates[l][qb][0][1] = caddf(cmulf(m1_00, m23_01), cmulf(m1_01, m23_11));
            gates[l][qb][1][0] = caddf(cmulf(m1_10, m23_00), cmulf(m1_11, m23_10));
            gates[l][qb][1][1] = caddf(cmulf(m1_10, m23_01), cmulf(m1_11, m23_11));
        } else if (t < 30) {
            int l = t - 24;
            float s, c;
            sincosf(wU[l], &s, &c);
            isc[l] = c;
            iss[l] = s;
        } else if (t == 30) {
            sScale = *scp;
        } else {
            sBias = *bip;
        }
        __syncwarp();

        // ---- phase B: column t of W in registers ----
        if (t < 16) {
            float2 col[16];
#pragma unroll
            for (int i = 0; i < 16; i++)
                col[i] = make_float2(i == t ? 1.f : 0.f, 0.f);

            const int PAIRS[12] = {1, 2, 1, 3, 1, 2, 1, 3, 0, 3, 0, 2};
#pragma unroll
            for (int l = 0; l < 6; l++) {
                int p = PAIRS[2 * l], q = PAIRS[2 * l + 1];
                int mp = 8 >> p, mq = 8 >> q;
                float c = isc[l], s = iss[l];
#pragma unroll
                for (int r = 0; r < 16; r++) {
                    if (r & (mp | mq)) continue;
                    int ia = r | mq, ib = r | mp;
                    float2 Av = col[ia], Bv = col[ib];
                    col[ia] = make_float2(c * Av.x - s * Bv.y, c * Av.y + s * Bv.x);
                    col[ib] = make_float2(c * Bv.x - s * Av.y, c * Bv.y + s * Av.x);
                }
#pragma unroll
                for (int qb = 0; qb < 4; qb++) {
                    int mask = 8 >> qb;
                    float2 g00 = gates[l][qb][0][0], g01 = gates[l][qb][0][1];
                    float2 g10 = gates[l][qb][1][0], g11 = gates[l][qb][1][1];
#pragma unroll
                    for (int r = 0; r < 16; r++) {
                        if (r & mask) continue;
                        float2 a0 = col[r], a1 = col[r | mask];
                        col[r]        = caddf(cmulf(g00, a0), cmulf(g01, a1));
                        col[r | mask] = caddf(cmulf(g10, a0), cmulf(g11, a1));
                    }
                }
            }
#pragma unroll
            for (int i = 0; i < 16; i++) sW[i][t] = col[i];
        }
        __syncwarp();

        // ---- phase C: popcount bins S_n[i] ----
        if (t < 16) {
            float2 S[5];
#pragma unroll
            for (int n = 0; n < 5; n++) S[n] = make_float2(0.f, 0.f);
#pragma unroll
            for (int a = 0; a < 16; a++) {
                int n = __popc(a);
                S[n] = caddf(S[n], sW[t][a]);
            }
#pragma unroll
            for (int n = 0; n < 5; n++) sS[t][n] = S[n];
        }
        __syncwarp();

        // ---- phase D: one coefficient pair per thread ----
        if (t < 15) {
            const int NA[15] = {0, 0, 0, 0, 0, 1, 1, 1, 1, 2, 2, 2, 3, 3, 4};
            const int NB[15] = {0, 1, 2, 3, 4, 1, 2, 3, 4, 2, 3, 4, 3, 4, 4};
            int na = NA[t], nb = NB[t];
            float gx = 0.f, gy = 0.f;
#pragma unroll
            for (int i = 0; i < 16; i++) {
                float m = (i < 8) ? 1.f : -1.f;
                float2 a = sS[i][na], b = sS[i][nb];
                gx += m * (a.x * b.x + a.y * b.y);
                gy += m * (a.x * b.y - a.y * b.x);
            }
            if (na == nb) { sA[t] = gx;       sB[t] = 0.f; }
            else          { sA[t] = 2.f * gx; sB[t] = -2.f * gy; }
        }
    }
    __syncthreads();

    // ---- eval: 2 elements per thread ----
    float A[15], B[15];
#pragma unroll
    for (int k = 0; k < 15; k++) { A[k] = sA[k]; B[k] = sB[k]; }
    const float scale = sScale;
    const float bias  = sBias;
    const float K = 0.011180339887f;  // sqrt(2/1000)/4

    int t = blockIdx.x * blockDim.x + threadIdx.x;
    float4 v = in[t];

    float Z0 = eval_one(v.x, v.y, A, B);
    float Z1 = eval_one(v.z, v.w, A, B);

    float2 r;
    r.x = fmaf(scale, fmaf(K, fmaf(Z0, Z0, -1.0f), Z0), bias);
    r.y = fmaf(scale, fmaf(K, fmaf(Z1, Z1, -1.0f), Z1), bias);
    out[t] = r;
}

// ---------------------------------------------------------------------------
extern "C" void kernel_launch(void* const* d_in, const int* in_sizes, int n_in,
                              void* d_out, int out_size) {
    const float* inputs = (const float*)d_in[0];  // [B,2] float32
    const float* wU     = (const float*)d_in[1];  // [6]
    const float* wR     = (const float*)d_in[2];  // [6,4,3]
    const float* sc     = (const float*)d_in[3];  // [] out_scale
    const float* bi     = (const float*)d_in[4];  // [] out_bias

    int nthreads = out_size / 2;  // 2 elements per thread
    int blocks = (nthreads + 255) / 256;
    fused_kernel<<<blocks, 256>>>((const float4*)inputs, wU, wR, sc, bi,
                                  (float2*)d_out);
}

// round 5
// speedup vs baseline: 1.6238x; 1.6238x over previous
#include <cuda_runtime.h>
#include <math.h>
#include <stdint.h>

// ---------------------------------------------------------------------------
// Model_25975962206896: 4-qubit VQC, B=524288.
// Z = s† (W† M W) s with s = v⊗v⊗v⊗v rank-1 ⇒ Z collapses to a 15-term
// trigonometric polynomial in (f0, f1). Two kernels:
//   setup_kernel: 1 block / 32 threads, fast-math float, register-resident W.
//   eval_kernel : 4 batch elements per thread, pure streaming + MUFU trig.
// ---------------------------------------------------------------------------

__device__ float g_cA[15];
__device__ float g_cB[15];

__device__ __forceinline__ float2 cmulf(float2 a, float2 b) {
    return make_float2(a.x * b.x - a.y * b.y, a.x * b.y + a.y * b.x);
}
__device__ __forceinline__ float2 caddf(float2 a, float2 b) {
    return make_float2(a.x + b.x, a.y + b.y);
}

// ---------------------------------------------------------------------------
// Setup kernel: 1 block, 32 threads, all float, all MUFU trig.
// ---------------------------------------------------------------------------
__global__ void setup_kernel(const float* __restrict__ wU,
                             const float* __restrict__ wR) {
    __shared__ float2 gates[6][4][2][2];
    __shared__ float  isc[6], iss[6];
    __shared__ float2 sW[16][16];   // sW[row i][col t]
    __shared__ float2 sS[16][5];    // popcount-binned row sums

    const int t = threadIdx.x;

    if (t < 24) {
        int l = t / 4, qb = t % 4;
        float a = wR[l * 12 + qb * 3 + 0];
        float b = wR[l * 12 + qb * 3 + 1];
        float c = wR[l * 12 + qb * 3 + 2];
        float sa, ca, sb, cb, sc3, cc3;
        __sincosf(0.5f * a, &sa, &ca);
        __sincosf(0.5f * b, &sb, &cb);
        __sincosf(0.5f * c, &sc3, &cc3);
        // g = RX(a) * RZ(b) * RX(c)
        float2 m1_00 = make_float2(ca, 0.f), m1_01 = make_float2(0.f, -sa);
        float2 m1_10 = make_float2(0.f, -sa), m1_11 = make_float2(ca, 0.f);
        float2 e0 = make_float2(cb, -sb), e1 = make_float2(cb, sb);
        float2 m3_00 = make_float2(cc3, 0.f), m3_01 = make_float2(0.f, -sc3);
        float2 m3_10 = make_float2(0.f, -sc3), m3_11 = make_float2(cc3, 0.f);
        float2 m23_00 = cmulf(e0, m3_00), m23_01 = cmulf(e0, m3_01);
        float2 m23_10 = cmulf(e1, m3_10), m23_11 = cmulf(e1, m3_11);
        gates[l][qb][0][0] = caddf(cmulf(m1_00, m23_00), cmulf(m1_01, m23_10));
        gates[l][qb][0][1] = caddf(cmulf(m1_00, m23_01), cmulf(m1_01, m23_11));
        gates[l][qb][1][0] = caddf(cmulf(m1_10, m23_00), cmulf(m1_11, m23_10));
        gates[l][qb][1][1] = caddf(cmulf(m1_10, m23_01), cmulf(m1_11, m23_11));
    } else if (t < 30) {
        int l = t - 24;
        float s, c;
        __sincosf(wU[l], &s, &c);
        isc[l] = c;
        iss[l] = s;
    }
    __syncthreads();

    // Build column t of W entirely in registers.
    if (t < 16) {
        float2 col[16];
#pragma unroll
        for (int i = 0; i < 16; i++)
            col[i] = make_float2(i == t ? 1.f : 0.f, 0.f);

        const int PAIRS[12] = {1, 2, 1, 3, 1, 2, 1, 3, 0, 3, 0, 2};
#pragma unroll
        for (int l = 0; l < 6; l++) {
            int p = PAIRS[2 * l], q = PAIRS[2 * l + 1];
            int mp = 8 >> p, mq = 8 >> q;
            float c = isc[l], s = iss[l];
#pragma unroll
            for (int r = 0; r < 16; r++) {
                if (r & (mp | mq)) continue;
                int ia = r | mq, ib = r | mp;
                float2 A = col[ia], B = col[ib];
                col[ia] = make_float2(c * A.x - s * B.y, c * A.y + s * B.x);
                col[ib] = make_float2(c * B.x - s * A.y, c * B.y + s * A.x);
            }
#pragma unroll
            for (int qb = 0; qb < 4; qb++) {
                int mask = 8 >> qb;
                float2 g00 = gates[l][qb][0][0], g01 = gates[l][qb][0][1];
                float2 g10 = gates[l][qb][1][0], g11 = gates[l][qb][1][1];
#pragma unroll
                for (int r = 0; r < 16; r++) {
                    if (r & mask) continue;
                    float2 a0 = col[r], a1 = col[r | mask];
                    col[r]        = caddf(cmulf(g00, a0), cmulf(g01, a1));
                    col[r | mask] = caddf(cmulf(g10, a0), cmulf(g11, a1));
                }
            }
        }
#pragma unroll
        for (int i = 0; i < 16; i++) sW[i][t] = col[i];
    }
    __syncthreads();

    // S_n[i] = sum over columns a with popcount(a)=n of W[i][a]
    if (t < 16) {
        float2 S[5];
#pragma unroll
        for (int n = 0; n < 5; n++) S[n] = make_float2(0.f, 0.f);
#pragma unroll
        for (int a = 0; a < 16; a++) {
            int n = __popc(a);
            S[n] = caddf(S[n], sW[t][a]);
        }
#pragma unroll
        for (int n = 0; n < 5; n++) sS[t][n] = S[n];
    }
    __syncthreads();

    // One coefficient pair per thread: G[na][nb] = sum_i M_i conj(S_na) S_nb
    if (t < 15) {
        const int NA[15] = {0, 0, 0, 0, 0, 1, 1, 1, 1, 2, 2, 2, 3, 3, 4};
        const int NB[15] = {0, 1, 2, 3, 4, 1, 2, 3, 4, 2, 3, 4, 3, 4, 4};
        int na = NA[t], nb = NB[t];
        float gx = 0.f, gy = 0.f;
#pragma unroll
        for (int i = 0; i < 16; i++) {
            float m = (i < 8) ? 1.f : -1.f;
            float2 a = sS[i][na], b = sS[i][nb];
            gx += m * (a.x * b.x + a.y * b.y);
            gy += m * (a.x * b.y - a.y * b.x);
        }
        if (na == nb) { g_cA[t] = gx;       g_cB[t] = 0.f; }
        else          { g_cA[t] = 2.f * gx; g_cB[t] = -2.f * gy; }
    }
}

// ---------------------------------------------------------------------------
// Per-element evaluation: 15-term trig polynomial, m-grouped.
// ---------------------------------------------------------------------------
__device__ __forceinline__ float eval_one(float f0, float f1,
                                          const float* __restrict__ A,
                                          const float* __restrict__ B) {
    float s, c, s1, c1;
    __sincosf(0.5f * f1, &s, &c);
    __sincosf(f0, &s1, &c1);

    float c2 = fmaf(2.0f * c1, c1, -1.0f);
    float s2 = 2.0f * s1 * c1;
    float c3 = fmaf(c2, c1, -s2 * s1);
    float s3 = fmaf(s2, c1, c2 * s1);
    float c4 = fmaf(c3, c1, -s3 * s1);
    float s4 = fmaf(s3, c1, c3 * s1);

    // w[p] = c^(8-p) * s^p via shallow product tree
    float cc = c * c, ss = s * s;
    float c4p = cc * cc, s4p = ss * ss;
    float c3p = cc * c, s3p = ss * s;
    float w0 = c4p * c4p;            // c^8
    float w1 = (c4p * c3p) * s;      // c^7 s
    float w2 = (c4p * cc) * ss;      // c^6 s^2
    float w3 = (c4p * c) * s3p;      // c^5 s^3
    float w4 = c4p * s4p;            // c^4 s^4
    float w5 = c3p * (s4p * s);      // c^3 s^5
    float w6 = cc * (s4p * ss);      // c^2 s^6
    float w7 = c * (s4p * s3p);      // c s^7
    float w8 = s4p * s4p;            // s^8

    // m=0 terms: k = 0,5,9,12,14 with p = 0,2,4,6,8
    float Z = A[0] * w0;
    Z = fmaf(A[5],  w2, Z);
    Z = fmaf(A[9],  w4, Z);
    Z = fmaf(A[12], w6, Z);
    Z = fmaf(A[14], w8, Z);
    // m=1: k = 1,6,10,13 with p = 1,3,5,7
    Z = fmaf(fmaf(A[1],  c1, B[1]  * s1), w1, Z);
    Z = fmaf(fmaf(A[6],  c1, B[6]  * s1), w3, Z);
    Z = fmaf(fmaf(A[10], c1, B[10] * s1), w5, Z);
    Z = fmaf(fmaf(A[13], c1, B[13] * s1), w7, Z);
    // m=2: k = 2,7,11 with p = 2,4,6
    Z = fmaf(fmaf(A[2],  c2, B[2]  * s2), w2, Z);
    Z = fmaf(fmaf(A[7],  c2, B[7]  * s2), w4, Z);
    Z = fmaf(fmaf(A[11], c2, B[11] * s2), w6, Z);
    // m=3: k = 3,8 with p = 3,5
    Z = fmaf(fmaf(A[3],  c3, B[3]  * s3), w3, Z);
    Z = fmaf(fmaf(A[8],  c3, B[8]  * s3), w5, Z);
    // m=4: k = 4, p = 4
    Z = fmaf(fmaf(A[4],  c4, B[4]  * s4), w4, Z);
    return Z;
}

// ---------------------------------------------------------------------------
// Eval kernel: 4 batch elements per thread (2x float4 in, 1x float4 out).
// ---------------------------------------------------------------------------
__global__ __launch_bounds__(256) void eval_kernel(
    const float4* __restrict__ in, const float* __restrict__ scp,
    const float* __restrict__ bip, float4* __restrict__ out) {
    float A[15], B[15];
#pragma unroll
    for (int k = 0; k < 15; k++) {
        A[k] = __ldg(&g_cA[k]);
        B[k] = __ldg(&g_cB[k]);
    }
    const float scale = __ldg(scp);
    const float bias  = __ldg(bip);
    const float K = 0.011180339887f;  // sqrt(2/1000)/4

    int t = blockIdx.x * blockDim.x + threadIdx.x;
    float4 v0 = in[2 * t];
    float4 v1 = in[2 * t + 1];

    float Z0 = eval_one(v0.x, v0.y, A, B);
    float Z1 = eval_one(v0.z, v0.w, A, B);
    float Z2 = eval_one(v1.x, v1.y, A, B);
    float Z3 = eval_one(v1.z, v1.w, A, B);

    float4 r;
    r.x = fmaf(scale, fmaf(K, fmaf(Z0, Z0, -1.0f), Z0), bias);
    r.y = fmaf(scale, fmaf(K, fmaf(Z1, Z1, -1.0f), Z1), bias);
    r.z = fmaf(scale, fmaf(K, fmaf(Z2, Z2, -1.0f), Z2), bias);
    r.w = fmaf(scale, fmaf(K, fmaf(Z3, Z3, -1.0f), Z3), bias);
    out[t] = r;
}

// ---------------------------------------------------------------------------
extern "C" void kernel_launch(void* const* d_in, const int* in_sizes, int n_in,
                              void* d_out, int out_size) {
    const float* inputs = (const float*)d_in[0];  // [B,2] float32
    const float* wU     = (const float*)d_in[1];  // [6]
    const float* wR     = (const float*)d_in[2];  // [6,4,3]
    const float* sc     = (const float*)d_in[3];  // [] out_scale
    const float* bi     = (const float*)d_in[4];  // [] out_bias

    setup_kernel<<<1, 32>>>(wU, wR);

    int nthreads = out_size / 4;  // 4 elements per thread
    int blocks = (nthreads + 255) / 256;
    eval_kernel<<<blocks, 256>>>((const float4*)inputs, sc, bi,
                                 (float4*)d_out);
}

// round 6
// speedup vs baseline: 2.8430x; 1.7509x over previous
#include <cuda_runtime.h>
#include <math.h>
#include <stdint.h>

// ---------------------------------------------------------------------------
// Model_25975962206896: 4-qubit VQC, B=524288.
// Z = s† (W† M W) s with s = v⊗v⊗v⊗v rank-1 ⇒ Z collapses to a 15-term
// trigonometric polynomial in (f0, f1).
//   setup_kernel: 1 block / 192 threads. Warps 0-4 propagate the 5 popcount
//                 indicator vectors u_n through the circuit via register
//                 state + __shfl_xor (one complex per thread, 30 steps).
//   eval_kernel : 4 batch elements per thread, grouped-by-power polynomial.
// ---------------------------------------------------------------------------

__device__ float g_cA[15];
__device__ float g_cB[15];

__device__ __forceinline__ float2 cmulf(float2 a, float2 b) {
    return make_float2(a.x * b.x - a.y * b.y, a.x * b.y + a.y * b.x);
}
__device__ __forceinline__ float2 caddf(float2 a, float2 b) {
    return make_float2(a.x + b.x, a.y + b.y);
}

// ---------------------------------------------------------------------------
// Setup kernel: 1 block, 192 threads.
//   warp 5 (threads 160..189): build 24 RXZX gates + 6 iSWAP sincos.
//   warps 0..4: bin n = warp id; lane r (0..15) holds amplitude S_n[r];
//               30 shuffle-steps apply the circuit.
//   threads 0..14: one coefficient pair each.
// ---------------------------------------------------------------------------
__global__ void setup_kernel(const float* __restrict__ wU,
                             const float* __restrict__ wR) {
    __shared__ float2 gates[6][4][2][2];
    __shared__ float  isc[6], iss[6];
    __shared__ float2 sS[16][5];    // S_n[i]

    const int tid = threadIdx.x;

    // ---- gate construction (warp 5) ----
    if (tid >= 160 && tid < 184) {
        int t = tid - 160;
        int l = t / 4, qb = t % 4;
        float a = wR[l * 12 + qb * 3 + 0];
        float b = wR[l * 12 + qb * 3 + 1];
        float c = wR[l * 12 + qb * 3 + 2];
        float sa, ca, sb, cb, sc3, cc3;
        __sincosf(0.5f * a, &sa, &ca);
        __sincosf(0.5f * b, &sb, &cb);
        __sincosf(0.5f * c, &sc3, &cc3);
        // g = RX(a) * RZ(b) * RX(c)
        float2 m1_00 = make_float2(ca, 0.f), m1_01 = make_float2(0.f, -sa);
        float2 m1_10 = make_float2(0.f, -sa), m1_11 = make_float2(ca, 0.f);
        float2 e0 = make_float2(cb, -sb), e1 = make_float2(cb, sb);
        float2 m3_00 = make_float2(cc3, 0.f), m3_01 = make_float2(0.f, -sc3);
        float2 m3_10 = make_float2(0.f, -sc3), m3_11 = make_float2(cc3, 0.f);
        float2 m23_00 = cmulf(e0, m3_00), m23_01 = cmulf(e0, m3_01);
        float2 m23_10 = cmulf(e1, m3_10), m23_11 = cmulf(e1, m3_11);
        gates[l][qb][0][0] = caddf(cmulf(m1_00, m23_00), cmulf(m1_01, m23_10));
        gates[l][qb][0][1] = caddf(cmulf(m1_00, m23_01), cmulf(m1_01, m23_11));
        gates[l][qb][1][0] = caddf(cmulf(m1_10, m23_00), cmulf(m1_11, m23_10));
        gates[l][qb][1][1] = caddf(cmulf(m1_10, m23_01), cmulf(m1_11, m23_11));
    } else if (tid >= 184 && tid < 190) {
        int l = tid - 184;
        float s, c;
        __sincosf(wU[l], &s, &c);
        isc[l] = c;
        iss[l] = s;
    }
    __syncthreads();

    // ---- propagate u_n via shuffles (warps 0..4) ----
    if (tid < 160) {
        const int n = tid >> 5;      // bin
        const int lane = tid & 31;
        const int r = lane & 15;     // basis state (lanes 16-31 mirror, unused)
        float2 z = make_float2((__popc(r) == n) ? 1.f : 0.f, 0.f);

        const int PAIRS[12] = {1, 2, 1, 3, 1, 2, 1, 3, 0, 3, 0, 2};
#pragma unroll
        for (int l = 0; l < 6; l++) {
            // iSWAP(theta) on (p,q): acts where bits differ; symmetric form
            {
                int mp = 8 >> PAIRS[2 * l], mq = 8 >> PAIRS[2 * l + 1];
                float c = isc[l], s = iss[l];
                float ox = __shfl_xor_sync(0xFFFFFFFFu, z.x, mp | mq);
                float oy = __shfl_xor_sync(0xFFFFFFFFu, z.y, mp | mq);
                bool act = ((r & mp) != 0) != ((r & mq) != 0);
                if (act)
                    z = make_float2(fmaf(c, z.x, -s * oy), fmaf(c, z.y, s * ox));
            }
            // per-qubit RXZX
#pragma unroll
            for (int qb = 0; qb < 4; qb++) {
                int mask = 8 >> qb;
                float ox = __shfl_xor_sync(0xFFFFFFFFu, z.x, mask);
                float oy = __shfl_xor_sync(0xFFFFFFFFu, z.y, mask);
                bool hi = (r & mask) != 0;
                float2 ga = hi ? gates[l][qb][1][1] : gates[l][qb][0][0];
                float2 gb = hi ? gates[l][qb][1][0] : gates[l][qb][0][1];
                float2 nz;
                nz.x = ga.x * z.x - ga.y * z.y + gb.x * ox - gb.y * oy;
                nz.y = ga.x * z.y + ga.y * z.x + gb.x * oy + gb.y * ox;
                z = nz;
            }
        }
        if (lane < 16) sS[r][n] = z;
    }
    __syncthreads();

    // ---- one coefficient pair per thread ----
    if (tid < 15) {
        const int NA[15] = {0, 0, 0, 0, 0, 1, 1, 1, 1, 2, 2, 2, 3, 3, 4};
        const int NB[15] = {0, 1, 2, 3, 4, 1, 2, 3, 4, 2, 3, 4, 3, 4, 4};
        int na = NA[tid], nb = NB[tid];
        float gx = 0.f, gy = 0.f;
#pragma unroll
        for (int i = 0; i < 16; i++) {
            float m = (i < 8) ? 1.f : -1.f;   // qubit 0 = bit 3
            float2 a = sS[i][na], b = sS[i][nb];
            gx += m * (a.x * b.x + a.y * b.y);
            gy += m * (a.x * b.y - a.y * b.x);
        }
        if (na == nb) { g_cA[tid] = gx;       g_cB[tid] = 0.f; }
        else          { g_cA[tid] = 2.f * gx; g_cB[tid] = -2.f * gy; }
    }
}

// ---------------------------------------------------------------------------
// Per-element evaluation, grouped by power p (shallow dependency tree).
// ---------------------------------------------------------------------------
__device__ __forceinline__ float eval_one(float f0, float f1,
                                          const float* __restrict__ A,
                                          const float* __restrict__ B) {
    float s, c, s1, c1;
    __sincosf(0.5f * f1, &s, &c);
    __sincosf(f0, &s1, &c1);

    float c2 = fmaf(2.0f * c1, c1, -1.0f);
    float s2 = 2.0f * s1 * c1;
    float c3 = fmaf(c2, c1, -s2 * s1);
    float s3 = fmaf(s2, c1, c2 * s1);
    float c4 = fmaf(c3, c1, -s3 * s1);
    float s4 = fmaf(s3, c1, c3 * s1);

    // w[p] = c^(8-p) * s^p via shallow product tree
    float cc = c * c, ss = s * s;
    float c4p = cc * cc, s4p = ss * ss;
    float c3p = cc * c, s3p = ss * s;
    float w0 = c4p * c4p;
    float w1 = (c4p * c3p) * s;
    float w2 = (c4p * cc) * ss;
    float w3 = (c4p * c) * s3p;
    float w4 = c4p * s4p;
    float w5 = c3p * (s4p * s);
    float w6 = cc * (s4p * ss);
    float w7 = c * (s4p * s3p);
    float w8 = s4p * s4p;

    // trig factors T_k = A_k cos(m f0) + B_k sin(m f0)
    float T1  = fmaf(A[1],  c1, B[1]  * s1);
    float T6  = fmaf(A[6],  c1, B[6]  * s1);
    float T10 = fmaf(A[10], c1, B[10] * s1);
    float T13 = fmaf(A[13], c1, B[13] * s1);
    float T2  = fmaf(A[2],  c2, B[2]  * s2);
    float T7  = fmaf(A[7],  c2, B[7]  * s2);
    float T11 = fmaf(A[11], c2, B[11] * s2);
    float T3  = fmaf(A[3],  c3, B[3]  * s3);
    float T8  = fmaf(A[8],  c3, B[8]  * s3);
    float T4  = fmaf(A[4],  c4, B[4]  * s4);

    // group by power p
    float G0 = A[0];
    float G1 = T1;
    float G2 = A[5] + T2;
    float G3 = T6 + T3;
    float G4 = A[9] + T7 + T4;
    float G5 = T10 + T8;
    float G6 = A[12] + T11;
    float G7 = T13;
    float G8 = A[14];

    // balanced accumulation
    float t0 = fmaf(w0, G0, w1 * G1);
    float t1 = fmaf(w2, G2, w3 * G3);
    float t2 = fmaf(w4, G4, w5 * G5);
    float t3 = fmaf(w6, G6, w7 * G7);
    float t4 = w8 * G8;
    return (t0 + t1) + (t2 + t3) + t4;
}

// ---------------------------------------------------------------------------
// Eval kernel: 4 batch elements per thread (2x float4 in, 1x float4 out),
// 128-thread blocks for higher block-per-SM count.
// ---------------------------------------------------------------------------
__global__ __launch_bounds__(128) void eval_kernel(
    const float4* __restrict__ in, const float* __restrict__ scp,
    const float* __restrict__ bip, float4* __restrict__ out) {
    float A[15], B[15];
#pragma unroll
    for (int k = 0; k < 15; k++) {
        A[k] = __ldg(&g_cA[k]);
        B[k] = __ldg(&g_cB[k]);
    }
    const float scale = __ldg(scp);
    const float bias  = __ldg(bip);
    const float K = 0.011180339887f;  // sqrt(2/1000)/4

    int t = blockIdx.x * blockDim.x + threadIdx.x;
    float4 v0 = in[2 * t];
    float4 v1 = in[2 * t + 1];

    float Z0 = eval_one(v0.x, v0.y, A, B);
    float Z1 = eval_one(v0.z, v0.w, A, B);
    float Z2 = eval_one(v1.x, v1.y, A, B);
    float Z3 = eval_one(v1.z, v1.w, A, B);

    float4 r;
    r.x = fmaf(scale, fmaf(K, fmaf(Z0, Z0, -1.0f), Z0), bias);
    r.y = fmaf(scale, fmaf(K, fmaf(Z1, Z1, -1.0f), Z1), bias);
    r.z = fmaf(scale, fmaf(K, fmaf(Z2, Z2, -1.0f), Z2), bias);
    r.w = fmaf(scale, fmaf(K, fmaf(Z3, Z3, -1.0f), Z3), bias);
    out[t] = r;
}

// ---------------------------------------------------------------------------
extern "C" void kernel_launch(void* const* d_in, const int* in_sizes, int n_in,
                              void* d_out, int out_size) {
    const float* inputs = (const float*)d_in[0];  // [B,2] float32
    const float* wU     = (const float*)d_in[1];  // [6]
    const float* wR     = (const float*)d_in[2];  // [6,4,3]
    const float* sc     = (const float*)d_in[3];  // [] out_scale
    const float* bi     = (const float*)d_in[4];  // [] out_bias

    setup_kernel<<<1, 192>>>(wU, wR);

    int nthreads = out_size / 4;  // 4 elements per thread
    int blocks = (nthreads + 127) / 128;
    eval_kernel<<<blocks, 128>>>((const float4*)inputs, sc, bi,
                                 (float4*)d_out);
}